// round 10
// baseline (speedup 1.0000x reference)
#include <cuda_runtime.h>
#include <stdint.h>

// Hash-grid trilinear interpolation — fused two-phase slicing, partials in SMEM.
//
// Each CTA owns PPC=4096 points. Phase 0: gather corners in table slice 0
// (vid top bit = 0) for all owned points, accumulate float4 partials and point
// meta {h, fx, fy, fz} in shared memory. __syncthreads. Phase 1: gather
// slice-1 corners, add the SMEM partial, write the final output.
//
// Why: R6-R9 established (a) slicing halves gather DRAM (64MB slice fits L2
// during its phase), (b) the two-kernel version pays a 128MB partial-sum DRAM
// round trip + double pts read, bounding it at ~520MB / ~100us. SMEM partials
// remove those bytes entirely. Phases stay grid-aligned statistically (equal
// work per CTA, CTAs in a wave start together).
//
// Thread layout: task = (pt_local, half-of-features); 1024 threads x 8 tasks.
// A task's corner-pair loads (vid, vid+1, same 16B half) are 32B apart ->
// same 128B line (L1 hit), keeping L1tex wavefronts at ~4/task.

#define BUCKETS_MASK ((1u << 22) - 1u)
#define SLICE_SHIFT 21
#define P1 1u
#define P2 2654435761u
#define P3 805459861u

#define BLOCK   1024
#define PPC     4096                 // points per CTA
#define NTASKS  (PPC * 2)            // (pt, half) tasks per CTA
#define ITERS   (NTASKS / BLOCK)     // 8

struct SmemLayout {
    float4 partial[NTASKS];          // 8192 * 16B = 128 KB
    float4 meta[PPC];                // {h-as-bits, fx, fy, fz}  64 KB
};

__device__ __forceinline__ void trilinear_weights(float fx, float fy, float fz, float* w) {
    float gx = 1.0f - fx, gy = 1.0f - fy, gz = 1.0f - fz;
    w[0] = gx * gy * gz;  w[1] = fx * gy * gz;
    w[2] = gx * fy * gz;  w[3] = fx * fy * gz;
    w[4] = gx * gy * fz;  w[5] = fx * gy * fz;
    w[6] = gx * fy * fz;  w[7] = fx * fy * fz;
}

__global__ void __launch_bounds__(BLOCK, 1) hashgrid_fused_kernel(
    const float* __restrict__ pts,   // (N,3)
    const char*  __restrict__ vf,    // (BUCKETS, 8 fp32) = 32 B per bucket
    float4*      __restrict__ out,   // (N, 8 fp32) = 2 float4 per point
    int n)
{
    extern __shared__ SmemLayout sm[];

    const uint32_t hoff[8] = {0u, P1, P2, P1 + P2, P3, P1 + P3, P2 + P3, P1 + P2 + P3};
    int base = blockIdx.x * PPC;

    // ---------------- Phase 0: slice 0 ----------------
#pragma unroll
    for (int it = 0; it < ITERS; it++) {
        int task = threadIdx.x + it * BLOCK;
        int pl   = task >> 1;
        int half = task & 1;
        int g    = base + pl;
        if (g >= n) break;

        float x = pts[3 * g + 0];
        float y = pts[3 * g + 1];
        float z = pts[3 * g + 2];

        float qx = x * 1024.0f, qy = y * 1024.0f, qz = z * 1024.0f;
        float bxf = floorf(qx), byf = floorf(qy), bzf = floorf(qz);
        float fx = qx - bxf, fy = qy - byf, fz = qz - bzf;

        uint32_t h = (uint32_t)(int)bxf * P1
                   + (uint32_t)(int)byf * P2
                   + (uint32_t)(int)bzf * P3;

        if (half == 0)
            sm->meta[pl] = make_float4(__uint_as_float(h), fx, fy, fz);

        float w[8];
        trilinear_weights(fx, fy, fz, w);

        const char* bptr = vf + ((uint32_t)half << 4);
        float4 f[8];
#pragma unroll
        for (int c = 0; c < 8; c++) {
            uint32_t vid = (h + hoff[c]) & BUCKETS_MASK;
            f[c] = make_float4(0.f, 0.f, 0.f, 0.f);
            if ((vid >> SLICE_SHIFT) == 0u)
                f[c] = __ldg((const float4*)(bptr + ((size_t)vid << 5)));
        }

        float4 acc = make_float4(0.f, 0.f, 0.f, 0.f);
#pragma unroll
        for (int c = 0; c < 8; c++) {
            acc.x = fmaf(w[c], f[c].x, acc.x);
            acc.y = fmaf(w[c], f[c].y, acc.y);
            acc.z = fmaf(w[c], f[c].z, acc.z);
            acc.w = fmaf(w[c], f[c].w, acc.w);
        }
        sm->partial[task] = acc;
    }

    __syncthreads();

    // ---------------- Phase 1: slice 1 ----------------
#pragma unroll
    for (int it = 0; it < ITERS; it++) {
        int task = threadIdx.x + it * BLOCK;
        int pl   = task >> 1;
        int half = task & 1;
        int g    = base + pl;
        if (g >= n) break;

        float4 m = sm->meta[pl];
        uint32_t h = __float_as_uint(m.x);
        float w[8];
        trilinear_weights(m.y, m.z, m.w, w);

        const char* bptr = vf + ((uint32_t)half << 4);
        float4 f[8];
#pragma unroll
        for (int c = 0; c < 8; c++) {
            uint32_t vid = (h + hoff[c]) & BUCKETS_MASK;
            f[c] = make_float4(0.f, 0.f, 0.f, 0.f);
            if ((vid >> SLICE_SHIFT) == 1u)
                f[c] = __ldg((const float4*)(bptr + ((size_t)vid << 5)));
        }

        float4 acc = sm->partial[task];
#pragma unroll
        for (int c = 0; c < 8; c++) {
            acc.x = fmaf(w[c], f[c].x, acc.x);
            acc.y = fmaf(w[c], f[c].y, acc.y);
            acc.z = fmaf(w[c], f[c].z, acc.z);
            acc.w = fmaf(w[c], f[c].w, acc.w);
        }
        __stcs(out + 2 * (size_t)g + half, acc);
    }
}

extern "C" void kernel_launch(void* const* d_in, const int* in_sizes, int n_in,
                              void* d_out, int out_size)
{
    const float* pts = (const float*)d_in[0];
    const char*  vf  = (const char*)d_in[1];
    float4*      out = (float4*)d_out;

    int n = in_sizes[0] / 3;

    static int smem_set = 0;
    int smem_bytes = (int)sizeof(SmemLayout);   // 192 KB
    if (!smem_set) {
        cudaFuncSetAttribute(hashgrid_fused_kernel,
                             cudaFuncAttributeMaxDynamicSharedMemorySize, smem_bytes);
        smem_set = 1;
    }

    int grid = (n + PPC - 1) / PPC;
    hashgrid_fused_kernel<<<grid, BLOCK, smem_bytes>>>(pts, vf, out, n);
}